// round 3
// baseline (speedup 1.0000x reference)
#include <cuda_runtime.h>
#include <cuda_bf16.h>
#include <math.h>

// Problem constants
#define B_   512
#define C_   2048
#define HW_  64
#define CF_  512
#define J_   30
#define D_   15450          // J*(CF+3)
#define EPS_ 1e-5f

// Output layout (flattened tuple concat):
// root (512*6) @0, pose (512*126) @3072, shape (512*10) @67584, cam (512*3) @72704

// ---- scratch (static device globals; no allocation APIs) ----
__device__ float g_pooled[B_ * C_];                 // 4 MB
__device__ float g_F[(size_t)B_ * HW_ * CF_];       // 67 MB, layout [b][hw][cf]
__device__ float g_feat[(size_t)B_ * D_];           // 31.6 MB
__device__ float g_part[6 * B_ * 132];              // ksplit partials

// ---- packed f32x2 helpers (Blackwell sm_100+) ----
__device__ __forceinline__ unsigned long long pk2(float lo, float hi) {
    unsigned long long r;
    asm("mov.b64 %0, {%1, %2};" : "=l"(r) : "f"(lo), "f"(hi));
    return r;
}
__device__ __forceinline__ void fma2(unsigned long long& d, unsigned long long a,
                                     unsigned long long b) {
    asm("fma.rn.f32x2 %0, %1, %2, %0;" : "+l"(d) : "l"(a), "l"(b));
}
__device__ __forceinline__ float2 upk(unsigned long long v) {
    float2 r;
    asm("mov.b64 {%0, %1}, %2;" : "=f"(r.x), "=f"(r.y) : "l"(v));
    return r;
}

// ============================================================
// K0: global average pool over HxW -> pooled (B, C)
// ============================================================
__global__ void k_pool(const float* __restrict__ img) {
    int i = blockIdx.x * 256 + threadIdx.x;   // over B*C
    if (i >= B_ * C_) return;
    const float4* p = (const float4*)(img + (size_t)i * HW_);
    float s = 0.f;
#pragma unroll
    for (int t = 0; t < 16; t++) {
        float4 v = p[t];
        s += v.x + v.y + v.z + v.w;
    }
    g_pooled[i] = s * (1.0f / 64.0f);
}

// ============================================================
// K0b: shape/cam heads. one block per batch, 128 threads
// ============================================================
__global__ void k_heads(const float* __restrict__ sw, const float* __restrict__ sb,
                        const float* __restrict__ cw, const float* __restrict__ cb,
                        float* __restrict__ out) {
    int b = blockIdx.x;
    __shared__ float pr[C_];
    for (int i = threadIdx.x; i < C_; i += 128) pr[i] = g_pooled[b * C_ + i];
    __syncthreads();
    int w = threadIdx.x >> 5, l = threadIdx.x & 31;
    for (int o = w; o < 13; o += 4) {
        const float* wr = (o < 10) ? (sw + (size_t)o * C_) : (cw + (size_t)(o - 10) * C_);
        float s = 0.f;
        for (int k = l; k < C_; k += 32) s += pr[k] * wr[k];
#pragma unroll
        for (int off = 16; off; off >>= 1) s += __shfl_xor_sync(0xffffffffu, s, off);
        if (l == 0) {
            if (o < 10) out[67584 + b * 10 + o] = s + sb[o];
            else        out[72704 + b * 3 + (o - 10)] = s + cb[o - 10];
        }
    }
}

// ============================================================
// K1: 1x1 conv + BN(eval) + ReLU  (batched GEMM, fp32x2 packed FMA)
// block: one batch, 128 output channels (M) x 64 positions (N), K=2048
// grid (4, 512), 256 threads (tx=n-group 16x4, ty=m-group 16x8)
// output F[b][hw][cf]  (cf contiguous for the gather kernel)
// ============================================================
#define KC1 32
__global__ void __launch_bounds__(256) k_conv(
    const float* __restrict__ img, const float* __restrict__ W,
    const float* __restrict__ cbias, const float* __restrict__ gam,
    const float* __restrict__ bet, const float* __restrict__ mu,
    const float* __restrict__ var) {
    int b = blockIdx.y;
    int m0 = blockIdx.x * 128;
    __shared__ float Wt[KC1][132];   // [k][m], padded (row 528B, 16B aligned)
    __shared__ float Xt[KC1][68];    // [k][n], padded (row 272B, 16B aligned)
    int tid = threadIdx.x;
    int tx = tid & 15;    // n: 4 each
    int ty = tid >> 4;    // m: 8 each (4 pairs)
    const float* Xb = img + (size_t)b * C_ * HW_;

    unsigned long long acc[4][4];  // [m-pair][n]
#pragma unroll
    for (int i = 0; i < 4; i++)
#pragma unroll
        for (int j = 0; j < 4; j++) acc[i][j] = 0ull;

    for (int k0 = 0; k0 < C_; k0 += KC1) {
        // load W tile 128(m) x 32(k), coalesced along k, store transposed
#pragma unroll
        for (int i = 0; i < 16; i++) {
            int idx = tid + i * 256;
            int m = idx >> 5, k = idx & 31;
            Wt[k][m] = W[(size_t)(m0 + m) * C_ + k0 + k];
        }
        // load X tile 32(k) x 64(n), coalesced along n
#pragma unroll
        for (int i = 0; i < 8; i++) {
            int idx = tid + i * 256;
            int k = idx >> 6, n = idx & 63;
            Xt[k][n] = Xb[(size_t)(k0 + k) * HW_ + n];
        }
        __syncthreads();
#pragma unroll
        for (int k = 0; k < KC1; k++) {
            unsigned long long ap[4];
#pragma unroll
            for (int i = 0; i < 4; i++)
                ap[i] = *(const unsigned long long*)&Wt[k][ty * 8 + 2 * i];
            float4 bv = *(const float4*)&Xt[k][tx * 4];
            unsigned long long bd[4];
            bd[0] = pk2(bv.x, bv.x); bd[1] = pk2(bv.y, bv.y);
            bd[2] = pk2(bv.z, bv.z); bd[3] = pk2(bv.w, bv.w);
#pragma unroll
            for (int i = 0; i < 4; i++)
#pragma unroll
                for (int j = 0; j < 4; j++) fma2(acc[i][j], ap[i], bd[j]);
        }
        __syncthreads();
    }

    // epilogue: BN + ReLU, write F[b][hw][cf]
    float* Fb = g_F + (size_t)b * HW_ * CF_;
#pragma unroll
    for (int i = 0; i < 4; i++) {
        int m = m0 + ty * 8 + 2 * i;
        float rs0 = rsqrtf(var[m] + EPS_),     rs1 = rsqrtf(var[m + 1] + EPS_);
        float s0 = gam[m] * rs0,               s1 = gam[m + 1] * rs1;
        float bb0 = bet[m] + (cbias[m] - mu[m]) * s0;
        float bb1 = bet[m + 1] + (cbias[m + 1] - mu[m + 1]) * s1;
#pragma unroll
        for (int j = 0; j < 4; j++) {
            float2 v = upk(acc[i][j]);
            float r0 = fmaxf(v.x * s0 + bb0, 0.f);
            float r1 = fmaxf(v.y * s1 + bb1, 0.f);
            int n = tx * 4 + j;
            *(float2*)&Fb[(size_t)n * CF_ + m] = make_float2(r0, r1);
        }
    }
}

// ============================================================
// K2: bilinear gather -> feat (B, J*515)
// ============================================================
__global__ void k_gather(const float* __restrict__ coords) {
    int b = blockIdx.x;
    __shared__ int   sidx[J_][4];
    __shared__ float swt[J_][4];
    int tid = threadIdx.x;  // 256
    if (tid < J_) {
        float x = coords[(b * J_ + tid) * 3 + 0];
        float y = coords[(b * J_ + tid) * 3 + 1];
        float x0f = floorf(x), y0f = floorf(y);
        float wx1 = x - x0f, wy1 = y - y0f;
        float wx0 = 1.f - wx1, wy0 = 1.f - wy1;
        int x0 = (int)x0f, y0 = (int)y0f, x1 = x0 + 1, y1 = y0 + 1;
        int ys[4] = {y0, y0, y1, y1};
        int xs[4] = {x0, x1, x0, x1};
        float ws[4] = {wy0 * wx0, wy0 * wx1, wy1 * wx0, wy1 * wx1};
#pragma unroll
        for (int c = 0; c < 4; c++) {
            bool valid = (xs[c] >= 0) && (xs[c] < 8) && (ys[c] >= 0) && (ys[c] < 8);
            int yc = min(max(ys[c], 0), 7), xc = min(max(xs[c], 0), 7);
            sidx[tid][c] = yc * 8 + xc;
            swt[tid][c] = valid ? ws[c] : 0.f;
        }
    }
    __syncthreads();
    const float* Fb = g_F + (size_t)b * HW_ * CF_;
    float* fb = g_feat + (size_t)b * D_;
    for (int j = 0; j < J_; j++) {
        int i0 = sidx[j][0], i1 = sidx[j][1], i2 = sidx[j][2], i3 = sidx[j][3];
        float w0 = swt[j][0], w1 = swt[j][1], w2 = swt[j][2], w3 = swt[j][3];
        for (int cf = tid; cf < CF_; cf += 256) {
            float v = w0 * Fb[i0 * CF_ + cf] + w1 * Fb[i1 * CF_ + cf]
                    + w2 * Fb[i2 * CF_ + cf] + w3 * Fb[i3 * CF_ + cf];
            fb[j * 515 + cf] = v;
        }
    }
    for (int t = tid; t < J_ * 3; t += 256) {
        int j = t / 3, c = t % 3;
        fb[j * 515 + 512 + c] = coords[(b * J_ + j) * 3 + c];
    }
}

// ============================================================
// K3: big linear heads (root 6 + pose 126 = 132 outputs), K=15450
// grid (ntile=5, btile=8, ksplit=6). Block: 64 batches x 32 outputs.
// K split on joint boundaries: 5 joints * 515 = 2575 per split.
// ============================================================
#define KC3 32
__global__ void __launch_bounds__(256) k_bigmm(const float* __restrict__ rw,
                                               const float* __restrict__ pw) {
    int o0 = blockIdx.x * 32;
    int b0 = blockIdx.y * 64;
    int ks = blockIdx.z;
    int kbeg = ks * 2575, kend = kbeg + 2575;
    __shared__ float At[KC3][65];  // [k][m], stride 65 -> conflict-free stores
    __shared__ float Bt[KC3][33];  // [k][n]
    int tid = threadIdx.x;
    int tx = tid & 7;    // n: 4 each -> 32
    int ty = tid >> 3;   // m: 2 each -> 64
    float acc[2][4];
#pragma unroll
    for (int i = 0; i < 2; i++)
#pragma unroll
        for (int j = 0; j < 4; j++) acc[i][j] = 0.f;

    for (int kk = kbeg; kk < kend; kk += KC3) {
        // A tile: 64(m) x 32(k)
#pragma unroll
        for (int i = 0; i < 8; i++) {
            int idx = tid + i * 256;
            int m = idx >> 5, k = idx & 31;
            int kg = kk + k;
            At[k][m] = (kg < kend) ? g_feat[(size_t)(b0 + m) * D_ + kg] : 0.f;
        }
        // B tile: 32(n=output) x 32(k)
#pragma unroll
        for (int i = 0; i < 4; i++) {
            int idx = tid + i * 256;
            int n = idx >> 5, k = idx & 31;
            int o = o0 + n, kg = kk + k;
            float v = 0.f;
            if (o < 132 && kg < kend) {
                const float* wr = (o < 6) ? (rw + (size_t)o * D_)
                                          : (pw + (size_t)(o - 6) * D_);
                v = wr[kg];
            }
            Bt[k][n] = v;
        }
        __syncthreads();
#pragma unroll
        for (int k = 0; k < KC3; k++) {
            float a0 = At[k][ty * 2], a1 = At[k][ty * 2 + 1];
#pragma unroll
            for (int j = 0; j < 4; j++) {
                float bj = Bt[k][tx * 4 + j];
                acc[0][j] += a0 * bj;
                acc[1][j] += a1 * bj;
            }
        }
        __syncthreads();
    }
#pragma unroll
    for (int i = 0; i < 2; i++) {
        int b = b0 + ty * 2 + i;
#pragma unroll
        for (int j = 0; j < 4; j++) {
            int o = o0 + tx * 4 + j;
            if (o < 132)
                g_part[((size_t)ks * B_ + b) * 132 + o] = acc[i][j];
        }
    }
}

__global__ void k_reduce(const float* __restrict__ rb, const float* __restrict__ pb,
                         float* __restrict__ out) {
    int i = blockIdx.x * 256 + threadIdx.x;
    if (i >= B_ * 132) return;
    int b = i / 132, o = i % 132;
    float s = 0.f;
#pragma unroll
    for (int ks = 0; ks < 6; ks++) s += g_part[((size_t)ks * B_ + b) * 132 + o];
    if (o < 6) out[b * 6 + o] = s + rb[o];
    else       out[3072 + b * 126 + (o - 6)] = s + pb[o - 6];
}

// ============================================================
extern "C" void kernel_launch(void* const* d_in, const int* in_sizes, int n_in,
                              void* d_out, int out_size) {
    const float* img    = (const float*)d_in[0];
    const float* coords = (const float*)d_in[1];
    const float* conv_w = (const float*)d_in[2];
    const float* conv_b = (const float*)d_in[3];
    const float* gam    = (const float*)d_in[4];
    const float* bet    = (const float*)d_in[5];
    const float* mu     = (const float*)d_in[6];
    const float* var    = (const float*)d_in[7];
    const float* root_w = (const float*)d_in[8];
    const float* root_b = (const float*)d_in[9];
    const float* pose_w = (const float*)d_in[10];
    const float* pose_b = (const float*)d_in[11];
    const float* shp_w  = (const float*)d_in[12];
    const float* shp_b  = (const float*)d_in[13];
    const float* cam_w  = (const float*)d_in[14];
    const float* cam_b  = (const float*)d_in[15];
    float* out = (float*)d_out;

    k_pool<<<(B_ * C_ + 255) / 256, 256>>>(img);
    k_heads<<<B_, 128>>>(shp_w, shp_b, cam_w, cam_b, out);
    k_conv<<<dim3(4, B_), 256>>>(img, conv_w, conv_b, gam, bet, mu, var);
    k_gather<<<B_, 256>>>(coords);
    k_bigmm<<<dim3(5, 8, 6), 256>>>(root_w, pose_w);
    k_reduce<<<(B_ * 132 + 255) / 256, 256>>>(root_b, pose_b, out);
}

// round 5
// speedup vs baseline: 1.2788x; 1.2788x over previous
#include <cuda_runtime.h>
#include <cuda_bf16.h>
#include <cstdint>
#include <math.h>

// Problem constants
#define B_   512
#define C_   2048
#define HW_  64
#define CF_  512
#define J_   30
#define D_   15450          // J*(CF+3)
#define EPS_ 1e-5f

// Output layout (flattened tuple concat):
// root (512*6) @0, pose (512*126) @3072, shape (512*10) @67584, cam (512*3) @72704

// ---- scratch (static device globals; no allocation APIs) ----
__device__ float g_pooled[B_ * C_];                       // 4 MB
__device__ float g_F[(size_t)B_ * HW_ * CF_];             // 67 MB [b][hw][cf]
__device__ float g_feat[(size_t)B_ * D_];                 // 31.6 MB
__device__ float g_part[6 * B_ * 132];
// W bf16 hi/lo: [seg][m=512][k=2048]
__device__ __align__(256) __nv_bfloat16 g_Wb[(size_t)2 * 512 * 2048];   // 4 MB

// =================== PTX helpers (sm_80+ ISA only) ===================
__device__ __forceinline__ uint32_t smem_u32(const void* p) {
    uint32_t a;
    asm("{ .reg .u64 t; cvta.to.shared.u64 t, %1; cvt.u32.u64 %0, t; }" : "=r"(a) : "l"(p));
    return a;
}
__device__ __forceinline__ void cpa16(uint32_t dst, const void* src) {
    asm volatile("cp.async.cg.shared.global [%0], [%1], 16;" :: "r"(dst), "l"(src));
}
#define CP_COMMIT() asm volatile("cp.async.commit_group;" ::: "memory")
#define CP_WAIT0()  asm volatile("cp.async.wait_group 0;" ::: "memory")

__device__ __forceinline__ void ldsm_x4(uint32_t (&r)[4], uint32_t addr) {
    asm volatile("ldmatrix.sync.aligned.m8n8.x4.shared.b16 {%0,%1,%2,%3}, [%4];"
        : "=r"(r[0]), "=r"(r[1]), "=r"(r[2]), "=r"(r[3]) : "r"(addr));
}
__device__ __forceinline__ void ldsm_x4t(uint32_t (&r)[4], uint32_t addr) {
    asm volatile("ldmatrix.sync.aligned.m8n8.x4.trans.shared.b16 {%0,%1,%2,%3}, [%4];"
        : "=r"(r[0]), "=r"(r[1]), "=r"(r[2]), "=r"(r[3]) : "r"(addr));
}
__device__ __forceinline__ void mma_bf16(float (&c)[4], const uint32_t (&a)[4],
                                         uint32_t b0, uint32_t b1) {
    asm volatile("mma.sync.aligned.m16n8k16.row.col.f32.bf16.bf16.f32 "
        "{%0,%1,%2,%3}, {%4,%5,%6,%7}, {%8,%9}, {%0,%1,%2,%3};"
        : "+f"(c[0]), "+f"(c[1]), "+f"(c[2]), "+f"(c[3])
        : "r"(a[0]), "r"(a[1]), "r"(a[2]), "r"(a[3]), "r"(b0), "r"(b1));
}

// ============================================================
// K_prep_w: conv_w fp32 -> bf16 hi/lo, [seg][m][k] row-major
// ============================================================
__global__ void __launch_bounds__(256) k_prep_w(const float* __restrict__ Wsrc) {
    int i = blockIdx.x * 256 + threadIdx.x;     // over 512*1024 float2
    int m = i >> 10, c2 = i & 1023;
    float2 v = *(const float2*)(Wsrc + (size_t)m * C_ + 2 * c2);
    __nv_bfloat16 h0 = __float2bfloat16(v.x), h1 = __float2bfloat16(v.y);
    __nv_bfloat16 l0 = __float2bfloat16(v.x - __bfloat162float(h0));
    __nv_bfloat16 l1 = __float2bfloat16(v.y - __bfloat162float(h1));
    __nv_bfloat162 ph; ph.x = h0; ph.y = h1;
    __nv_bfloat162 pl; pl.x = l0; pl.y = l1;
    size_t off = (size_t)m * 2048 + 2 * c2;
    *(__nv_bfloat162*)(g_Wb + off) = ph;
    *(__nv_bfloat162*)(g_Wb + (size_t)512 * 2048 + off) = pl;
}

// ============================================================
// K0: global average pool over HxW -> pooled (B, C)
// ============================================================
__global__ void k_pool(const float* __restrict__ img) {
    int i = blockIdx.x * 256 + threadIdx.x;
    if (i >= B_ * C_) return;
    const float4* p = (const float4*)(img + (size_t)i * HW_);
    float s = 0.f;
#pragma unroll
    for (int t = 0; t < 16; t++) {
        float4 v = p[t];
        s += v.x + v.y + v.z + v.w;
    }
    g_pooled[i] = s * (1.0f / 64.0f);
}

// ============================================================
// K0b: shape/cam heads
// ============================================================
__global__ void k_heads(const float* __restrict__ sw, const float* __restrict__ sb,
                        const float* __restrict__ cw, const float* __restrict__ cb,
                        float* __restrict__ out) {
    int b = blockIdx.x;
    __shared__ float pr[C_];
    for (int i = threadIdx.x; i < C_; i += 128) pr[i] = g_pooled[b * C_ + i];
    __syncthreads();
    int w = threadIdx.x >> 5, l = threadIdx.x & 31;
    for (int o = w; o < 13; o += 4) {
        const float* wr = (o < 10) ? (sw + (size_t)o * C_) : (cw + (size_t)(o - 10) * C_);
        float s = 0.f;
        for (int k = l; k < C_; k += 32) s += pr[k] * wr[k];
#pragma unroll
        for (int off = 16; off; off >>= 1) s += __shfl_xor_sync(0xffffffffu, s, off);
        if (l == 0) {
            if (o < 10) out[67584 + b * 10 + o] = s + sb[o];
            else        out[72704 + b * 3 + (o - 10)] = s + cb[o - 10];
        }
    }
}

// ============================================================
// K1: conv GEMM on tensor pipe via mma.sync (bf16 hi/lo split)
// Block: M=128 cf x N=256 (4 batches x 64 hw), K=2048, KC=32 chunks.
// grid (4 cf-tiles, 128 batch-groups), 256 threads (8 warps, 2m x 4n).
// SMEM (dynamic, 141312 B):
//   Ahi[2] @0      (2 x 10240: 128 rows x 80B)
//   Alo[2] @20480
//   Bhi[2] @40960  (2 x 16896: 32 rows x 528B)
//   Blo[2] @74752
//   Xraw  @108544  (32768: 8192 fp32)
// ============================================================
#define A_TILE 10240
#define B_TILE 16896
#define OFF_ALO 20480
#define OFF_BHI 40960
#define OFF_BLO 74752
#define OFF_XRW 108544
#define SMEM_CONV 141312

__global__ void __launch_bounds__(256, 1) k_conv_mma(
    const float* __restrict__ img, const float* __restrict__ cbias,
    const float* __restrict__ gam, const float* __restrict__ bet,
    const float* __restrict__ mu, const float* __restrict__ var) {
    extern __shared__ __align__(16) char dsm[];
    const int tid = threadIdx.x;
    const int m0 = blockIdx.x * 128;
    const int b0 = blockIdx.y * 4;
    const uint32_t sbase = smem_u32(dsm);

    float acc[4][8][4];
#pragma unroll
    for (int i = 0; i < 4; i++)
#pragma unroll
        for (int j = 0; j < 8; j++)
#pragma unroll
            for (int r = 0; r < 4; r++) acc[i][j][r] = 0.f;

    // ---- cp.async issue for chunk kc into buffer nb ----
    auto issue_chunk = [&](int kc, int nb) {
        int k0 = kc * 32;
        // W hi/lo: 128 rows x 64B each seg; thread: row=tid>>1, half=tid&1 (32B x2)
        int row = tid >> 1, half = tid & 1;
        const __nv_bfloat16* wh = g_Wb + (size_t)(m0 + row) * 2048 + k0 + half * 16;
        const __nv_bfloat16* wl = wh + (size_t)512 * 2048;
        uint32_t da = sbase + nb * A_TILE + row * 80 + half * 32;
        cpa16(da, wh);
        cpa16(da + 16, wh + 8);
        uint32_t dl = sbase + OFF_ALO + nb * A_TILE + row * 80 + half * 32;
        cpa16(dl, wl);
        cpa16(dl + 16, wl + 8);
        // X fp32: 4 batches x 32c x 64hw = 8192 floats; thread: 8 x 16B
#pragma unroll
        for (int q = 0; q < 8; q++) {
            int e0 = (tid * 8 + q) * 4;
            int j = e0 >> 11, c = (e0 >> 6) & 31, hw = e0 & 63;
            const float* src = img + ((size_t)(b0 + j) * C_ + k0 + c) * HW_ + hw;
            cpa16(sbase + OFF_XRW + e0 * 4, src);
        }
        CP_COMMIT();
    };

    // ---- convert Xraw -> Bhi/Blo in buffer nb ----
    auto convert_x = [&](int nb) {
        const float4* Xq = (const float4*)(dsm + OFF_XRW);
        char* bh = dsm + OFF_BHI + nb * B_TILE;
        char* bl = dsm + OFF_BLO + nb * B_TILE;
#pragma unroll
        for (int q = 0; q < 8; q++) {
            float4 v = Xq[tid * 8 + q];
            int e0 = (tid * 8 + q) * 4;
            int j = e0 >> 11, c = (e0 >> 6) & 31, hw = e0 & 63;
            __nv_bfloat16 h0 = __float2bfloat16(v.x), h1 = __float2bfloat16(v.y);
            __nv_bfloat16 h2 = __float2bfloat16(v.z), h3 = __float2bfloat16(v.w);
            __nv_bfloat16 l0 = __float2bfloat16(v.x - __bfloat162float(h0));
            __nv_bfloat16 l1 = __float2bfloat16(v.y - __bfloat162float(h1));
            __nv_bfloat16 l2 = __float2bfloat16(v.z - __bfloat162float(h2));
            __nv_bfloat16 l3 = __float2bfloat16(v.w - __bfloat162float(h3));
            __nv_bfloat162 ph01; ph01.x = h0; ph01.y = h1;
            __nv_bfloat162 ph23; ph23.x = h2; ph23.y = h3;
            __nv_bfloat162 pl01; pl01.x = l0; pl01.y = l1;
            __nv_bfloat162 pl23; pl23.x = l2; pl23.y = l3;
            int off = c * 528 + (j * 64 + hw) * 2;
            *(uint2*)(bh + off) = make_uint2(*(uint32_t*)&ph01, *(uint32_t*)&ph23);
            *(uint2*)(bl + off) = make_uint2(*(uint32_t*)&pl01, *(uint32_t*)&pl23);
        }
    };

    const int w = tid >> 5, lane = tid & 31;
    const int wm = (w >> 2) * 64;
    const int wn = (w & 3) * 64;
    const int lrow = lane & 15, lsel = lane >> 4;

    // ---- compute one chunk from buffer nb ----
    auto compute = [&](int nb) {
        uint32_t Ah = sbase + nb * A_TILE;
        uint32_t Al = sbase + OFF_ALO + nb * A_TILE;
        uint32_t Bh = sbase + OFF_BHI + nb * B_TILE;
        uint32_t Bl = sbase + OFF_BLO + nb * B_TILE;
#pragma unroll
        for (int ks = 0; ks < 2; ks++) {
            uint32_t ahi[4][4], alo[4][4], bhi[4][4], blo[4][4];
            int acol = (ks * 16 + lsel * 8) * 2;
            int arow = wm + lrow;
#pragma unroll
            for (int i = 0; i < 4; i++) {
                ldsm_x4(ahi[i], Ah + (arow + i * 16) * 80 + acol);
                ldsm_x4(alo[i], Al + (arow + i * 16) * 80 + acol);
            }
            int brow = (ks * 16 + lrow) * 528;
            int bcol0 = (wn + lsel * 8) * 2;
#pragma unroll
            for (int j = 0; j < 4; j++) {
                ldsm_x4t(bhi[j], Bh + brow + bcol0 + j * 32);
                ldsm_x4t(blo[j], Bl + brow + bcol0 + j * 32);
            }
#pragma unroll
            for (int i = 0; i < 4; i++)
#pragma unroll
                for (int jj = 0; jj < 8; jj++) {
                    uint32_t b0r = bhi[jj >> 1][(jj & 1) * 2];
                    uint32_t b1r = bhi[jj >> 1][(jj & 1) * 2 + 1];
                    mma_bf16(acc[i][jj], ahi[i], b0r, b1r);
                    mma_bf16(acc[i][jj], alo[i], b0r, b1r);
                    uint32_t c0r = blo[jj >> 1][(jj & 1) * 2];
                    uint32_t c1r = blo[jj >> 1][(jj & 1) * 2 + 1];
                    mma_bf16(acc[i][jj], ahi[i], c0r, c1r);
                }
        }
    };

    // prologue
    issue_chunk(0, 0);
    CP_WAIT0();
    __syncthreads();
    convert_x(0);
    __syncthreads();

    for (int kc = 0; kc < 64; kc++) {
        int nb = kc & 1;
        if (kc < 63) issue_chunk(kc + 1, nb ^ 1);
        compute(nb);
        if (kc < 63) {
            CP_WAIT0();
            __syncthreads();
            convert_x(nb ^ 1);
            __syncthreads();
        }
    }

    // epilogue: BN + ReLU -> g_F[b][hw][cf]
    int jb = w & 3;
    int gid = lane >> 2, tig = lane & 3;
    float* Fb = g_F + (size_t)(b0 + jb) * HW_ * CF_;
#pragma unroll
    for (int i = 0; i < 4; i++) {
        int cfA = m0 + wm + i * 16 + gid;
        int cfB = cfA + 8;
        float scA = gam[cfA] * rsqrtf(var[cfA] + EPS_);
        float bbA = bet[cfA] + (cbias[cfA] - mu[cfA]) * scA;
        float scB = gam[cfB] * rsqrtf(var[cfB] + EPS_);
        float bbB = bet[cfB] + (cbias[cfB] - mu[cfB]) * scB;
#pragma unroll
        for (int jj = 0; jj < 8; jj++) {
            int hw = jj * 8 + tig * 2;
            Fb[(size_t)hw * CF_ + cfA]       = fmaxf(fmaf(acc[i][jj][0], scA, bbA), 0.f);
            Fb[(size_t)(hw + 1) * CF_ + cfA] = fmaxf(fmaf(acc[i][jj][1], scA, bbA), 0.f);
            Fb[(size_t)hw * CF_ + cfB]       = fmaxf(fmaf(acc[i][jj][2], scB, bbB), 0.f);
            Fb[(size_t)(hw + 1) * CF_ + cfB] = fmaxf(fmaf(acc[i][jj][3], scB, bbB), 0.f);
        }
    }
}

// ============================================================
// K2: bilinear gather -> feat (B, J*515)
// ============================================================
__global__ void k_gather(const float* __restrict__ coords) {
    int b = blockIdx.x;
    __shared__ int   sidx[J_][4];
    __shared__ float swt[J_][4];
    int tid = threadIdx.x;  // 256
    if (tid < J_) {
        float x = coords[(b * J_ + tid) * 3 + 0];
        float y = coords[(b * J_ + tid) * 3 + 1];
        float x0f = floorf(x), y0f = floorf(y);
        float wx1 = x - x0f, wy1 = y - y0f;
        float wx0 = 1.f - wx1, wy0 = 1.f - wy1;
        int x0 = (int)x0f, y0 = (int)y0f, x1 = x0 + 1, y1 = y0 + 1;
        int ys[4] = {y0, y0, y1, y1};
        int xs[4] = {x0, x1, x0, x1};
        float ws[4] = {wy0 * wx0, wy0 * wx1, wy1 * wx0, wy1 * wx1};
#pragma unroll
        for (int c = 0; c < 4; c++) {
            bool valid = (xs[c] >= 0) && (xs[c] < 8) && (ys[c] >= 0) && (ys[c] < 8);
            int yc = min(max(ys[c], 0), 7), xc = min(max(xs[c], 0), 7);
            sidx[tid][c] = yc * 8 + xc;
            swt[tid][c] = valid ? ws[c] : 0.f;
        }
    }
    __syncthreads();
    const float* Fb = g_F + (size_t)b * HW_ * CF_;
    float* fb = g_feat + (size_t)b * D_;
    for (int j = 0; j < J_; j++) {
        int i0 = sidx[j][0], i1 = sidx[j][1], i2 = sidx[j][2], i3 = sidx[j][3];
        float w0 = swt[j][0], w1 = swt[j][1], w2 = swt[j][2], w3 = swt[j][3];
        for (int cf = tid; cf < CF_; cf += 256) {
            float v = w0 * Fb[i0 * CF_ + cf] + w1 * Fb[i1 * CF_ + cf]
                    + w2 * Fb[i2 * CF_ + cf] + w3 * Fb[i3 * CF_ + cf];
            fb[j * 515 + cf] = v;
        }
    }
    for (int t = tid; t < J_ * 3; t += 256) {
        int j = t / 3, c = t % 3;
        fb[j * 515 + 512 + c] = coords[(b * J_ + j) * 3 + c];
    }
}

// ============================================================
// K3: big linear heads (root 6 + pose 126), K=15450, ksplit=6
// ============================================================
#define KC3 32
__global__ void __launch_bounds__(256) k_bigmm(const float* __restrict__ rw,
                                               const float* __restrict__ pw) {
    int o0 = blockIdx.x * 32;
    int b0 = blockIdx.y * 64;
    int ks = blockIdx.z;
    int kbeg = ks * 2575, kend = kbeg + 2575;
    __shared__ float At[KC3][65];
    __shared__ float Bt[KC3][33];
    int tid = threadIdx.x;
    int tx = tid & 7;
    int ty = tid >> 3;
    float acc[2][4];
#pragma unroll
    for (int i = 0; i < 2; i++)
#pragma unroll
        for (int j = 0; j < 4; j++) acc[i][j] = 0.f;

    for (int kk = kbeg; kk < kend; kk += KC3) {
#pragma unroll
        for (int i = 0; i < 8; i++) {
            int idx = tid + i * 256;
            int m = idx >> 5, k = idx & 31;
            int kg = kk + k;
            At[k][m] = (kg < kend) ? g_feat[(size_t)(b0 + m) * D_ + kg] : 0.f;
        }
#pragma unroll
        for (int i = 0; i < 4; i++) {
            int idx = tid + i * 256;
            int n = idx >> 5, k = idx & 31;
            int o = o0 + n, kg = kk + k;
            float v = 0.f;
            if (o < 132 && kg < kend) {
                const float* wr = (o < 6) ? (rw + (size_t)o * D_)
                                          : (pw + (size_t)(o - 6) * D_);
                v = wr[kg];
            }
            Bt[k][n] = v;
        }
        __syncthreads();
#pragma unroll
        for (int k = 0; k < KC3; k++) {
            float a0 = At[k][ty * 2], a1 = At[k][ty * 2 + 1];
#pragma unroll
            for (int j = 0; j < 4; j++) {
                float bj = Bt[k][tx * 4 + j];
                acc[0][j] += a0 * bj;
                acc[1][j] += a1 * bj;
            }
        }
        __syncthreads();
    }
#pragma unroll
    for (int i = 0; i < 2; i++) {
        int b = b0 + ty * 2 + i;
#pragma unroll
        for (int j = 0; j < 4; j++) {
            int o = o0 + tx * 4 + j;
            if (o < 132)
                g_part[((size_t)ks * B_ + b) * 132 + o] = acc[i][j];
        }
    }
}

__global__ void k_reduce(const float* __restrict__ rb, const float* __restrict__ pb,
                         float* __restrict__ out) {
    int i = blockIdx.x * 256 + threadIdx.x;
    if (i >= B_ * 132) return;
    int b = i / 132, o = i % 132;
    float s = 0.f;
#pragma unroll
    for (int ks = 0; ks < 6; ks++) s += g_part[((size_t)ks * B_ + b) * 132 + o];
    if (o < 6) out[b * 6 + o] = s + rb[o];
    else       out[3072 + b * 126 + (o - 6)] = s + pb[o - 6];
}

// ============================================================
extern "C" void kernel_launch(void* const* d_in, const int* in_sizes, int n_in,
                              void* d_out, int out_size) {
    const float* img    = (const float*)d_in[0];
    const float* coords = (const float*)d_in[1];
    const float* conv_w = (const float*)d_in[2];
    const float* conv_b = (const float*)d_in[3];
    const float* gam    = (const float*)d_in[4];
    const float* bet    = (const float*)d_in[5];
    const float* mu     = (const float*)d_in[6];
    const float* var    = (const float*)d_in[7];
    const float* root_w = (const float*)d_in[8];
    const float* root_b = (const float*)d_in[9];
    const float* pose_w = (const float*)d_in[10];
    const float* pose_b = (const float*)d_in[11];
    const float* shp_w  = (const float*)d_in[12];
    const float* shp_b  = (const float*)d_in[13];
    const float* cam_w  = (const float*)d_in[14];
    const float* cam_b  = (const float*)d_in[15];
    float* out = (float*)d_out;

    cudaFuncSetAttribute(k_conv_mma, cudaFuncAttributeMaxDynamicSharedMemorySize, SMEM_CONV);

    k_prep_w<<<2048, 256>>>(conv_w);
    k_pool<<<(B_ * C_ + 255) / 256, 256>>>(img);
    k_heads<<<B_, 128>>>(shp_w, shp_b, cam_w, cam_b, out);
    k_conv_mma<<<dim3(4, 128), 256, SMEM_CONV>>>(img, conv_b, gam, bet, mu, var);
    k_gather<<<B_, 256>>>(coords);
    k_bigmm<<<dim3(5, 8, 6), 256>>>(root_w, pose_w);
    k_reduce<<<(B_ * 132 + 255) / 256, 256>>>(root_b, pose_b, out);
}

// round 6
// speedup vs baseline: 2.0288x; 1.5866x over previous
#include <cuda_runtime.h>
#include <cuda_bf16.h>
#include <cstdint>
#include <math.h>

// Problem constants
#define B_   512
#define C_   2048
#define HW_  64
#define CF_  512
#define J_   30
#define D_   15450          // J*(CF+3)
#define EPS_ 1e-5f

// Output layout (flattened tuple concat):
// root (512*6) @0, pose (512*126) @3072, shape (512*10) @67584, cam (512*3) @72704

// ---- scratch (static device globals; no allocation APIs) ----
__device__ float g_pooled[B_ * C_];                       // 4 MB
__device__ float g_F[(size_t)B_ * HW_ * CF_];             // 67 MB [b][hw][cf]
__device__ float g_feat[(size_t)B_ * D_];                 // 31.6 MB
__device__ float g_part[6 * B_ * 132];
// W bf16 hi/lo: [seg][m=512][k=2048]
__device__ __align__(256) __nv_bfloat16 g_Wb[(size_t)2 * 512 * 2048];      // 4 MB
// X bf16 hi/lo: [seg][b][c][hw]  (same layout as img, bf16)
__device__ __align__(256) __nv_bfloat16 g_Xb[(size_t)2 * B_ * C_ * HW_];   // 268 MB

// =================== PTX helpers (sm_80+ ISA only) ===================
__device__ __forceinline__ uint32_t smem_u32(const void* p) {
    uint32_t a;
    asm("{ .reg .u64 t; cvta.to.shared.u64 t, %1; cvt.u32.u64 %0, t; }" : "=r"(a) : "l"(p));
    return a;
}
__device__ __forceinline__ void cpa16(uint32_t dst, const void* src) {
    asm volatile("cp.async.cg.shared.global [%0], [%1], 16;" :: "r"(dst), "l"(src));
}
#define CP_COMMIT() asm volatile("cp.async.commit_group;" ::: "memory")
#define CP_WAIT0()  asm volatile("cp.async.wait_group 0;" ::: "memory")

__device__ __forceinline__ void ldsm_x4(uint32_t (&r)[4], uint32_t addr) {
    asm volatile("ldmatrix.sync.aligned.m8n8.x4.shared.b16 {%0,%1,%2,%3}, [%4];"
        : "=r"(r[0]), "=r"(r[1]), "=r"(r[2]), "=r"(r[3]) : "r"(addr));
}
__device__ __forceinline__ void ldsm_x4t(uint32_t (&r)[4], uint32_t addr) {
    asm volatile("ldmatrix.sync.aligned.m8n8.x4.trans.shared.b16 {%0,%1,%2,%3}, [%4];"
        : "=r"(r[0]), "=r"(r[1]), "=r"(r[2]), "=r"(r[3]) : "r"(addr));
}
__device__ __forceinline__ void mma_bf16(float (&c)[4], const uint32_t (&a)[4],
                                         uint32_t b0, uint32_t b1) {
    asm volatile("mma.sync.aligned.m16n8k16.row.col.f32.bf16.bf16.f32 "
        "{%0,%1,%2,%3}, {%4,%5,%6,%7}, {%8,%9}, {%0,%1,%2,%3};"
        : "+f"(c[0]), "+f"(c[1]), "+f"(c[2]), "+f"(c[3])
        : "r"(a[0]), "r"(a[1]), "r"(a[2]), "r"(a[3]), "r"(b0), "r"(b1));
}

// ============================================================
// K_prep_w: conv_w fp32 -> bf16 hi/lo, [seg][m][k] row-major
// ============================================================
__global__ void __launch_bounds__(256) k_prep_w(const float* __restrict__ Wsrc) {
    int i = blockIdx.x * 256 + threadIdx.x;     // over 512*1024 float2
    int m = i >> 10, c2 = i & 1023;
    float2 v = *(const float2*)(Wsrc + (size_t)m * C_ + 2 * c2);
    __nv_bfloat16 h0 = __float2bfloat16(v.x), h1 = __float2bfloat16(v.y);
    __nv_bfloat16 l0 = __float2bfloat16(v.x - __bfloat162float(h0));
    __nv_bfloat16 l1 = __float2bfloat16(v.y - __bfloat162float(h1));
    __nv_bfloat162 ph; ph.x = h0; ph.y = h1;
    __nv_bfloat162 pl; pl.x = l0; pl.y = l1;
    size_t off = (size_t)m * 2048 + 2 * c2;
    *(__nv_bfloat162*)(g_Wb + off) = ph;
    *(__nv_bfloat162*)(g_Wb + (size_t)512 * 2048 + off) = pl;
}

// ============================================================
// K_prep_x: img fp32 -> bf16 hi/lo (same layout) + fused global pool
// each thread handles 4 consecutive floats (16 threads per hw-row)
// ============================================================
__global__ void __launch_bounds__(256) k_prep_x(const float* __restrict__ img) {
    size_t i = (size_t)blockIdx.x * 256 + threadIdx.x;   // over 16.8M float4
    float4 v = ((const float4*)img)[i];
    __nv_bfloat16 h0 = __float2bfloat16(v.x), h1 = __float2bfloat16(v.y);
    __nv_bfloat16 h2 = __float2bfloat16(v.z), h3 = __float2bfloat16(v.w);
    __nv_bfloat16 l0 = __float2bfloat16(v.x - __bfloat162float(h0));
    __nv_bfloat16 l1 = __float2bfloat16(v.y - __bfloat162float(h1));
    __nv_bfloat16 l2 = __float2bfloat16(v.z - __bfloat162float(h2));
    __nv_bfloat16 l3 = __float2bfloat16(v.w - __bfloat162float(h3));
    __nv_bfloat162 a; a.x = h0; a.y = h1;
    __nv_bfloat162 b; b.x = h2; b.y = h3;
    __nv_bfloat162 c; c.x = l0; c.y = l1;
    __nv_bfloat162 d; d.x = l2; d.y = l3;
    *(uint2*)(g_Xb + i * 4) = make_uint2(*(uint32_t*)&a, *(uint32_t*)&b);
    *(uint2*)(g_Xb + (size_t)B_ * C_ * HW_ + i * 4) = make_uint2(*(uint32_t*)&c, *(uint32_t*)&d);
    // fused pool: 16 threads cover one (b,c) row of 64
    float s = v.x + v.y + v.z + v.w;
#pragma unroll
    for (int off = 1; off < 16; off <<= 1) s += __shfl_xor_sync(0xffffffffu, s, off);
    if ((threadIdx.x & 15) == 0) g_pooled[i >> 4] = s * (1.0f / 64.0f);
}

// ============================================================
// K0b: shape/cam heads
// ============================================================
__global__ void k_heads(const float* __restrict__ sw, const float* __restrict__ sb,
                        const float* __restrict__ cw, const float* __restrict__ cb,
                        float* __restrict__ out) {
    int b = blockIdx.x;
    __shared__ float pr[C_];
    for (int i = threadIdx.x; i < C_; i += 128) pr[i] = g_pooled[b * C_ + i];
    __syncthreads();
    int w = threadIdx.x >> 5, l = threadIdx.x & 31;
    for (int o = w; o < 13; o += 4) {
        const float* wr = (o < 10) ? (sw + (size_t)o * C_) : (cw + (size_t)(o - 10) * C_);
        float s = 0.f;
        for (int k = l; k < C_; k += 32) s += pr[k] * wr[k];
#pragma unroll
        for (int off = 16; off; off >>= 1) s += __shfl_xor_sync(0xffffffffu, s, off);
        if (l == 0) {
            if (o < 10) out[67584 + b * 10 + o] = s + sb[o];
            else        out[72704 + b * 3 + (o - 10)] = s + cb[o - 10];
        }
    }
}

// ============================================================
// K1: conv GEMM via mma.sync, bf16 hi/lo pre-converted.
// Block: M=128 cf x N=256 (4 batches x 64 hw), K=2048, 64 chunks of 32.
// 512 threads (16 warps: 4m x 4n, warp tile 32x64).
// SMEM: Ahi/Alo per buf (10240 each), Bhi/Blo per buf (16896 each)
//   A: buf*20480 + seg*10240   (rows 80B = 64 data + 16 pad)
//   B: 40960 + buf*33792 + seg*16896  (rows 528B = 512 data + 16 pad)
// ============================================================
#define A_SEG 10240
#define B_SEG 16896
#define OFF_B 40960
#define SMEM_CONV 108544

__global__ void __launch_bounds__(512, 1) k_conv_mma(
    const float* __restrict__ cbias,
    const float* __restrict__ gam, const float* __restrict__ bet,
    const float* __restrict__ mu, const float* __restrict__ var) {
    extern __shared__ __align__(16) char dsm[];
    const int tid = threadIdx.x;
    const int m0 = blockIdx.x * 128;
    const int b0 = blockIdx.y * 4;
    const uint32_t sbase = smem_u32(dsm);

    float acc[2][8][4];
#pragma unroll
    for (int i = 0; i < 2; i++)
#pragma unroll
        for (int j = 0; j < 8; j++)
#pragma unroll
            for (int r = 0; r < 4; r++) acc[i][j][r] = 0.f;

    // ---- cp.async issue for chunk kc into buffer nb ----
    auto issue_chunk = [&](int kc, int nb) {
        int k0 = kc * 32;
        // A: 2 segs x 128 rows x 64B ; thread: row=tid>>2, q=tid&3
        int row = tid >> 2, q = tid & 3;
#pragma unroll
        for (int seg = 0; seg < 2; seg++) {
            const __nv_bfloat16* src =
                g_Wb + (size_t)seg * (512 * 2048) + (size_t)(m0 + row) * 2048 + k0 + q * 8;
            cpa16(sbase + nb * 20480 + seg * A_SEG + row * 80 + q * 16, src);
        }
        // B: 2 segs x (32k x 4j x 128B) ; 2 iters: idx -> k, j, q
#pragma unroll
        for (int t = 0; t < 2; t++) {
            int idx = tid + t * 512;
            int k = idx >> 5, r = idx & 31;
            int j = r >> 3, qq = r & 7;
#pragma unroll
            for (int seg = 0; seg < 2; seg++) {
                const __nv_bfloat16* src =
                    g_Xb + ((size_t)(seg * B_ + b0 + j) * C_ + k0 + k) * HW_ + qq * 8;
                cpa16(sbase + OFF_B + nb * 33792 + seg * B_SEG + k * 528 + j * 128 + qq * 16,
                      src);
            }
        }
        CP_COMMIT();
    };

    const int w = tid >> 5, lane = tid & 31;
    const int wm = (w >> 2) * 32;
    const int wn = (w & 3) * 64;
    const int lrow = lane & 15, lsel = lane >> 4;

    // ---- compute one chunk from buffer nb (staged hi/lo to cap live regs) ----
    auto compute = [&](int nb) {
        uint32_t Ah = sbase + nb * 20480;
        uint32_t Al = Ah + A_SEG;
        uint32_t Bh = sbase + OFF_B + nb * 33792;
        uint32_t Bl = Bh + B_SEG;
#pragma unroll
        for (int ks = 0; ks < 2; ks++) {
            int acol = (ks * 16 + lsel * 8) * 2;
            int arow = wm + lrow;
            int brow = (ks * 16 + lrow) * 528;
            int bcol0 = (wn + lsel * 8) * 2;
            uint32_t ahi[2][4], bhi[4][4];
#pragma unroll
            for (int i = 0; i < 2; i++) ldsm_x4(ahi[i], Ah + (arow + i * 16) * 80 + acol);
#pragma unroll
            for (int j = 0; j < 4; j++) ldsm_x4t(bhi[j], Bh + brow + bcol0 + j * 32);
#pragma unroll
            for (int i = 0; i < 2; i++)
#pragma unroll
                for (int jj = 0; jj < 8; jj++)
                    mma_bf16(acc[i][jj], ahi[i],
                             bhi[jj >> 1][(jj & 1) * 2], bhi[jj >> 1][(jj & 1) * 2 + 1]);
            {
                uint32_t alo[2][4];
#pragma unroll
                for (int i = 0; i < 2; i++) ldsm_x4(alo[i], Al + (arow + i * 16) * 80 + acol);
#pragma unroll
                for (int i = 0; i < 2; i++)
#pragma unroll
                    for (int jj = 0; jj < 8; jj++)
                        mma_bf16(acc[i][jj], alo[i],
                                 bhi[jj >> 1][(jj & 1) * 2], bhi[jj >> 1][(jj & 1) * 2 + 1]);
            }
            {
                uint32_t blo[4][4];
#pragma unroll
                for (int j = 0; j < 4; j++) ldsm_x4t(blo[j], Bl + brow + bcol0 + j * 32);
#pragma unroll
                for (int i = 0; i < 2; i++)
#pragma unroll
                    for (int jj = 0; jj < 8; jj++)
                        mma_bf16(acc[i][jj], ahi[i],
                                 blo[jj >> 1][(jj & 1) * 2], blo[jj >> 1][(jj & 1) * 2 + 1]);
            }
        }
    };

    // prologue
    issue_chunk(0, 0);
    CP_WAIT0();
    __syncthreads();

    for (int kc = 0; kc < 64; kc++) {
        int nb = kc & 1;
        if (kc < 63) issue_chunk(kc + 1, nb ^ 1);
        compute(nb);
        if (kc < 63) {
            CP_WAIT0();
            __syncthreads();
        }
    }

    // epilogue: BN + ReLU -> g_F[b][hw][cf]
    int jb = w & 3;
    int gid = lane >> 2, tig = lane & 3;
    float* Fb = g_F + (size_t)(b0 + jb) * HW_ * CF_;
#pragma unroll
    for (int i = 0; i < 2; i++) {
        int cfA = m0 + wm + i * 16 + gid;
        int cfB = cfA + 8;
        float scA = gam[cfA] * rsqrtf(var[cfA] + EPS_);
        float bbA = bet[cfA] + (cbias[cfA] - mu[cfA]) * scA;
        float scB = gam[cfB] * rsqrtf(var[cfB] + EPS_);
        float bbB = bet[cfB] + (cbias[cfB] - mu[cfB]) * scB;
#pragma unroll
        for (int jj = 0; jj < 8; jj++) {
            int hw = jj * 8 + tig * 2;
            Fb[(size_t)hw * CF_ + cfA]       = fmaxf(fmaf(acc[i][jj][0], scA, bbA), 0.f);
            Fb[(size_t)(hw + 1) * CF_ + cfA] = fmaxf(fmaf(acc[i][jj][1], scA, bbA), 0.f);
            Fb[(size_t)hw * CF_ + cfB]       = fmaxf(fmaf(acc[i][jj][2], scB, bbB), 0.f);
            Fb[(size_t)(hw + 1) * CF_ + cfB] = fmaxf(fmaf(acc[i][jj][3], scB, bbB), 0.f);
        }
    }
}

// ============================================================
// K2: bilinear gather -> feat (B, J*515)
// ============================================================
__global__ void k_gather(const float* __restrict__ coords) {
    int b = blockIdx.x;
    __shared__ int   sidx[J_][4];
    __shared__ float swt[J_][4];
    int tid = threadIdx.x;  // 256
    if (tid < J_) {
        float x = coords[(b * J_ + tid) * 3 + 0];
        float y = coords[(b * J_ + tid) * 3 + 1];
        float x0f = floorf(x), y0f = floorf(y);
        float wx1 = x - x0f, wy1 = y - y0f;
        float wx0 = 1.f - wx1, wy0 = 1.f - wy1;
        int x0 = (int)x0f, y0 = (int)y0f, x1 = x0 + 1, y1 = y0 + 1;
        int ys[4] = {y0, y0, y1, y1};
        int xs[4] = {x0, x1, x0, x1};
        float ws[4] = {wy0 * wx0, wy0 * wx1, wy1 * wx0, wy1 * wx1};
#pragma unroll
        for (int c = 0; c < 4; c++) {
            bool valid = (xs[c] >= 0) && (xs[c] < 8) && (ys[c] >= 0) && (ys[c] < 8);
            int yc = min(max(ys[c], 0), 7), xc = min(max(xs[c], 0), 7);
            sidx[tid][c] = yc * 8 + xc;
            swt[tid][c] = valid ? ws[c] : 0.f;
        }
    }
    __syncthreads();
    const float* Fb = g_F + (size_t)b * HW_ * CF_;
    float* fb = g_feat + (size_t)b * D_;
    for (int j = 0; j < J_; j++) {
        int i0 = sidx[j][0], i1 = sidx[j][1], i2 = sidx[j][2], i3 = sidx[j][3];
        float w0 = swt[j][0], w1 = swt[j][1], w2 = swt[j][2], w3 = swt[j][3];
        for (int cf = tid; cf < CF_; cf += 256) {
            float v = w0 * Fb[i0 * CF_ + cf] + w1 * Fb[i1 * CF_ + cf]
                    + w2 * Fb[i2 * CF_ + cf] + w3 * Fb[i3 * CF_ + cf];
            fb[j * 515 + cf] = v;
        }
    }
    for (int t = tid; t < J_ * 3; t += 256) {
        int j = t / 3, c = t % 3;
        fb[j * 515 + 512 + c] = coords[(b * J_ + j) * 3 + c];
    }
}

// ============================================================
// K3: big linear heads (root 6 + pose 126), K=15450, ksplit=6
// ============================================================
#define KC3 32
__global__ void __launch_bounds__(256) k_bigmm(const float* __restrict__ rw,
                                               const float* __restrict__ pw) {
    int o0 = blockIdx.x * 32;
    int b0 = blockIdx.y * 64;
    int ks = blockIdx.z;
    int kbeg = ks * 2575, kend = kbeg + 2575;
    __shared__ float At[KC3][65];
    __shared__ float Bt[KC3][33];
    int tid = threadIdx.x;
    int tx = tid & 7;
    int ty = tid >> 3;
    float acc[2][4];
#pragma unroll
    for (int i = 0; i < 2; i++)
#pragma unroll
        for (int j = 0; j < 4; j++) acc[i][j] = 0.f;

    for (int kk = kbeg; kk < kend; kk += KC3) {
#pragma unroll
        for (int i = 0; i < 8; i++) {
            int idx = tid + i * 256;
            int m = idx >> 5, k = idx & 31;
            int kg = kk + k;
            At[k][m] = (kg < kend) ? g_feat[(size_t)(b0 + m) * D_ + kg] : 0.f;
        }
#pragma unroll
        for (int i = 0; i < 4; i++) {
            int idx = tid + i * 256;
            int n = idx >> 5, k = idx & 31;
            int o = o0 + n, kg = kk + k;
            float v = 0.f;
            if (o < 132 && kg < kend) {
                const float* wr = (o < 6) ? (rw + (size_t)o * D_)
                                          : (pw + (size_t)(o - 6) * D_);
                v = wr[kg];
            }
            Bt[k][n] = v;
        }
        __syncthreads();
#pragma unroll
        for (int k = 0; k < KC3; k++) {
            float a0 = At[k][ty * 2], a1 = At[k][ty * 2 + 1];
#pragma unroll
            for (int j = 0; j < 4; j++) {
                float bj = Bt[k][tx * 4 + j];
                acc[0][j] += a0 * bj;
                acc[1][j] += a1 * bj;
            }
        }
        __syncthreads();
    }
#pragma unroll
    for (int i = 0; i < 2; i++) {
        int b = b0 + ty * 2 + i;
#pragma unroll
        for (int j = 0; j < 4; j++) {
            int o = o0 + tx * 4 + j;
            if (o < 132)
                g_part[((size_t)ks * B_ + b) * 132 + o] = acc[i][j];
        }
    }
}

__global__ void k_reduce(const float* __restrict__ rb, const float* __restrict__ pb,
                         float* __restrict__ out) {
    int i = blockIdx.x * 256 + threadIdx.x;
    if (i >= B_ * 132) return;
    int b = i / 132, o = i % 132;
    float s = 0.f;
#pragma unroll
    for (int ks = 0; ks < 6; ks++) s += g_part[((size_t)ks * B_ + b) * 132 + o];
    if (o < 6) out[b * 6 + o] = s + rb[o];
    else       out[3072 + b * 126 + (o - 6)] = s + pb[o - 6];
}

// ============================================================
extern "C" void kernel_launch(void* const* d_in, const int* in_sizes, int n_in,
                              void* d_out, int out_size) {
    const float* img    = (const float*)d_in[0];
    const float* coords = (const float*)d_in[1];
    const float* conv_w = (const float*)d_in[2];
    const float* conv_b = (const float*)d_in[3];
    const float* gam    = (const float*)d_in[4];
    const float* bet    = (const float*)d_in[5];
    const float* mu     = (const float*)d_in[6];
    const float* var    = (const float*)d_in[7];
    const float* root_w = (const float*)d_in[8];
    const float* root_b = (const float*)d_in[9];
    const float* pose_w = (const float*)d_in[10];
    const float* pose_b = (const float*)d_in[11];
    const float* shp_w  = (const float*)d_in[12];
    const float* shp_b  = (const float*)d_in[13];
    const float* cam_w  = (const float*)d_in[14];
    const float* cam_b  = (const float*)d_in[15];
    float* out = (float*)d_out;

    cudaFuncSetAttribute(k_conv_mma, cudaFuncAttributeMaxDynamicSharedMemorySize, SMEM_CONV);

    k_prep_w<<<2048, 256>>>(conv_w);
    k_prep_x<<<65536, 256>>>(img);                   // also computes g_pooled
    k_heads<<<B_, 128>>>(shp_w, shp_b, cam_w, cam_b, out);
    k_conv_mma<<<dim3(4, 128), 512, SMEM_CONV>>>(conv_b, gam, bet, mu, var);
    k_gather<<<B_, 256>>>(coords);
    k_bigmm<<<dim3(5, 8, 6), 256>>>(root_w, pose_w);
    k_reduce<<<(B_ * 132 + 255) / 256, 256>>>(root_b, pose_b, out);
}

// round 7
// speedup vs baseline: 2.2768x; 1.1222x over previous
#include <cuda_runtime.h>
#include <cuda_bf16.h>
#include <cstdint>
#include <math.h>

// Problem constants
#define B_   512
#define C_   2048
#define HW_  64
#define CF_  512
#define J_   30
#define D_   15450          // J*(CF+3)
#define EPS_ 1e-5f

// Output layout (flattened tuple concat):
// root (512*6) @0, pose (512*126) @3072, shape (512*10) @67584, cam (512*3) @72704

// ---- scratch (static device globals; no allocation APIs) ----
__device__ float g_pooled[B_ * C_];                       // 4 MB
__device__ float g_F[(size_t)B_ * HW_ * CF_];             // 67 MB [b][hw][cf]
__device__ float g_feat[(size_t)B_ * D_];                 // 31.6 MB
__device__ float g_part[6 * B_ * 132];
// W bf16 hi/lo: [seg][m=512][k=2048]
__device__ __align__(256) __nv_bfloat16 g_Wb[(size_t)2 * 512 * 2048];      // 4 MB
// X bf16 hi/lo: [seg][b][c][hw]  (same layout as img, bf16)
__device__ __align__(256) __nv_bfloat16 g_Xb[(size_t)2 * B_ * C_ * HW_];   // 268 MB

// =================== PTX helpers (sm_80+ ISA only) ===================
__device__ __forceinline__ uint32_t smem_u32(const void* p) {
    uint32_t a;
    asm("{ .reg .u64 t; cvta.to.shared.u64 t, %1; cvt.u32.u64 %0, t; }" : "=r"(a) : "l"(p));
    return a;
}
__device__ __forceinline__ void cpa16(uint32_t dst, const void* src) {
    asm volatile("cp.async.cg.shared.global [%0], [%1], 16;" :: "r"(dst), "l"(src));
}
#define CP_COMMIT() asm volatile("cp.async.commit_group;" ::: "memory")
#define CP_WAIT0()  asm volatile("cp.async.wait_group 0;" ::: "memory")

__device__ __forceinline__ void ldsm_x4(uint32_t (&r)[4], uint32_t addr) {
    asm volatile("ldmatrix.sync.aligned.m8n8.x4.shared.b16 {%0,%1,%2,%3}, [%4];"
        : "=r"(r[0]), "=r"(r[1]), "=r"(r[2]), "=r"(r[3]) : "r"(addr));
}
__device__ __forceinline__ void ldsm_x4t(uint32_t (&r)[4], uint32_t addr) {
    asm volatile("ldmatrix.sync.aligned.m8n8.x4.trans.shared.b16 {%0,%1,%2,%3}, [%4];"
        : "=r"(r[0]), "=r"(r[1]), "=r"(r[2]), "=r"(r[3]) : "r"(addr));
}
__device__ __forceinline__ void mma_bf16(float (&c)[4], const uint32_t (&a)[4],
                                         uint32_t b0, uint32_t b1) {
    asm volatile("mma.sync.aligned.m16n8k16.row.col.f32.bf16.bf16.f32 "
        "{%0,%1,%2,%3}, {%4,%5,%6,%7}, {%8,%9}, {%0,%1,%2,%3};"
        : "+f"(c[0]), "+f"(c[1]), "+f"(c[2]), "+f"(c[3])
        : "r"(a[0]), "r"(a[1]), "r"(a[2]), "r"(a[3]), "r"(b0), "r"(b1));
}

// ============================================================
// K_prep_w: conv_w fp32 -> bf16 hi/lo, [seg][m][k] row-major
// ============================================================
__global__ void __launch_bounds__(256) k_prep_w(const float* __restrict__ Wsrc) {
    int i = blockIdx.x * 256 + threadIdx.x;     // over 512*1024 float2
    int m = i >> 10, c2 = i & 1023;
    float2 v = *(const float2*)(Wsrc + (size_t)m * C_ + 2 * c2);
    __nv_bfloat16 h0 = __float2bfloat16(v.x), h1 = __float2bfloat16(v.y);
    __nv_bfloat16 l0 = __float2bfloat16(v.x - __bfloat162float(h0));
    __nv_bfloat16 l1 = __float2bfloat16(v.y - __bfloat162float(h1));
    __nv_bfloat162 ph; ph.x = h0; ph.y = h1;
    __nv_bfloat162 pl; pl.x = l0; pl.y = l1;
    size_t off = (size_t)m * 2048 + 2 * c2;
    *(__nv_bfloat162*)(g_Wb + off) = ph;
    *(__nv_bfloat162*)(g_Wb + (size_t)512 * 2048 + off) = pl;
}

// ============================================================
// K_prep_x: img fp32 -> bf16 hi/lo (same layout) + fused global pool
// ============================================================
__global__ void __launch_bounds__(256) k_prep_x(const float* __restrict__ img) {
    size_t i = (size_t)blockIdx.x * 256 + threadIdx.x;   // over 16.8M float4
    float4 v = ((const float4*)img)[i];
    __nv_bfloat16 h0 = __float2bfloat16(v.x), h1 = __float2bfloat16(v.y);
    __nv_bfloat16 h2 = __float2bfloat16(v.z), h3 = __float2bfloat16(v.w);
    __nv_bfloat16 l0 = __float2bfloat16(v.x - __bfloat162float(h0));
    __nv_bfloat16 l1 = __float2bfloat16(v.y - __bfloat162float(h1));
    __nv_bfloat16 l2 = __float2bfloat16(v.z - __bfloat162float(h2));
    __nv_bfloat16 l3 = __float2bfloat16(v.w - __bfloat162float(h3));
    __nv_bfloat162 a; a.x = h0; a.y = h1;
    __nv_bfloat162 b; b.x = h2; b.y = h3;
    __nv_bfloat162 c; c.x = l0; c.y = l1;
    __nv_bfloat162 d; d.x = l2; d.y = l3;
    *(uint2*)(g_Xb + i * 4) = make_uint2(*(uint32_t*)&a, *(uint32_t*)&b);
    *(uint2*)(g_Xb + (size_t)B_ * C_ * HW_ + i * 4) = make_uint2(*(uint32_t*)&c, *(uint32_t*)&d);
    // fused pool: 16 threads cover one (b,c) row of 64
    float s = v.x + v.y + v.z + v.w;
#pragma unroll
    for (int off = 1; off < 16; off <<= 1) s += __shfl_xor_sync(0xffffffffu, s, off);
    if ((threadIdx.x & 15) == 0) g_pooled[i >> 4] = s * (1.0f / 64.0f);
}

// ============================================================
// K0b: shape/cam heads
// ============================================================
__global__ void k_heads(const float* __restrict__ sw, const float* __restrict__ sb,
                        const float* __restrict__ cw, const float* __restrict__ cb,
                        float* __restrict__ out) {
    int b = blockIdx.x;
    __shared__ float pr[C_];
    for (int i = threadIdx.x; i < C_; i += 128) pr[i] = g_pooled[b * C_ + i];
    __syncthreads();
    int w = threadIdx.x >> 5, l = threadIdx.x & 31;
    for (int o = w; o < 13; o += 4) {
        const float* wr = (o < 10) ? (sw + (size_t)o * C_) : (cw + (size_t)(o - 10) * C_);
        float s = 0.f;
        for (int k = l; k < C_; k += 32) s += pr[k] * wr[k];
#pragma unroll
        for (int off = 16; off; off >>= 1) s += __shfl_xor_sync(0xffffffffu, s, off);
        if (l == 0) {
            if (o < 10) out[67584 + b * 10 + o] = s + sb[o];
            else        out[72704 + b * 3 + (o - 10)] = s + cb[o - 10];
        }
    }
}

// ============================================================
// K1: conv GEMM via mma.sync, bf16 hi/lo pre-converted.
// CTA: M=128 cf x N=128 (2 batches x 64 hw), K=2048, 64 chunks of 32.
// 256 threads (8 warps: 4m x 2n, warp tile 32x64), 2 CTAs/SM.
// SMEM 75776 B:
//   A: buf*20480 + seg*10240   (128 rows x 80B = 64B data + 16 pad)
//   B: 40960 + buf*17408 + seg*8704  (32 rows x 272B = 256B data + 16 pad)
// ============================================================
#define A_SEG 10240
#define B_SEG 8704
#define OFF_B 40960
#define SMEM_CONV 75776

__global__ void __launch_bounds__(256, 2) k_conv_mma(
    const float* __restrict__ cbias,
    const float* __restrict__ gam, const float* __restrict__ bet,
    const float* __restrict__ mu, const float* __restrict__ var) {
    extern __shared__ __align__(16) char dsm[];
    const int tid = threadIdx.x;
    const int m0 = blockIdx.x * 128;
    const int b0 = blockIdx.y * 2;
    const uint32_t sbase = smem_u32(dsm);

    float acc[2][8][4];
#pragma unroll
    for (int i = 0; i < 2; i++)
#pragma unroll
        for (int j = 0; j < 8; j++)
#pragma unroll
            for (int r = 0; r < 4; r++) acc[i][j][r] = 0.f;

    // ---- cp.async issue for chunk kc into buffer nb ----
    auto issue_chunk = [&](int kc, int nb) {
        int k0 = kc * 32;
        // A: 2 segs x 128 rows x 64B = 512 cpa16/seg; 2 per thread per seg
#pragma unroll
        for (int t = 0; t < 2; t++) {
            int idx = tid + t * 256;
            int row = idx >> 2, q = idx & 3;
#pragma unroll
            for (int seg = 0; seg < 2; seg++) {
                const __nv_bfloat16* src =
                    g_Wb + (size_t)seg * (512 * 2048) + (size_t)(m0 + row) * 2048 + k0 + q * 8;
                cpa16(sbase + nb * 20480 + seg * A_SEG + row * 80 + q * 16, src);
            }
        }
        // B: 2 segs x 32k x 256B = 512 cpa16/seg
#pragma unroll
        for (int t = 0; t < 2; t++) {
            int idx = tid + t * 256;
            int k = idx >> 4, r = idx & 15;       // r: 16B chunk within 256B row
            int j = r >> 3, hwq = r & 7;
#pragma unroll
            for (int seg = 0; seg < 2; seg++) {
                const __nv_bfloat16* src =
                    g_Xb + ((size_t)(seg * B_ + b0 + j) * C_ + k0 + k) * HW_ + hwq * 8;
                cpa16(sbase + OFF_B + nb * 17408 + seg * B_SEG + k * 272 + r * 16, src);
            }
        }
        CP_COMMIT();
    };

    const int w = tid >> 5, lane = tid & 31;
    const int wm = (w >> 1) * 32;
    const int wn = (w & 1) * 64;
    const int lrow = lane & 15, lsel = lane >> 4;

    // ---- compute one chunk from buffer nb (staged hi/lo to cap live regs) ----
    auto compute = [&](int nb) {
        uint32_t Ah = sbase + nb * 20480;
        uint32_t Al = Ah + A_SEG;
        uint32_t Bh = sbase + OFF_B + nb * 17408;
        uint32_t Bl = Bh + B_SEG;
#pragma unroll
        for (int ks = 0; ks < 2; ks++) {
            int acol = (ks * 16 + lsel * 8) * 2;
            int arow = wm + lrow;
            int brow = (ks * 16 + lrow) * 272;
            int bcol0 = (wn + lsel * 8) * 2;
            uint32_t ahi[2][4], bhi[4][4];
#pragma unroll
            for (int i = 0; i < 2; i++) ldsm_x4(ahi[i], Ah + (arow + i * 16) * 80 + acol);
#pragma unroll
            for (int j = 0; j < 4; j++) ldsm_x4t(bhi[j], Bh + brow + bcol0 + j * 32);
#pragma unroll
            for (int i = 0; i < 2; i++)
#pragma unroll
                for (int jj = 0; jj < 8; jj++)
                    mma_bf16(acc[i][jj], ahi[i],
                             bhi[jj >> 1][(jj & 1) * 2], bhi[jj >> 1][(jj & 1) * 2 + 1]);
            {
                uint32_t alo[2][4];
#pragma unroll
                for (int i = 0; i < 2; i++) ldsm_x4(alo[i], Al + (arow + i * 16) * 80 + acol);
#pragma unroll
                for (int i = 0; i < 2; i++)
#pragma unroll
                    for (int jj = 0; jj < 8; jj++)
                        mma_bf16(acc[i][jj], alo[i],
                                 bhi[jj >> 1][(jj & 1) * 2], bhi[jj >> 1][(jj & 1) * 2 + 1]);
            }
            {
                uint32_t blo[4][4];
#pragma unroll
                for (int j = 0; j < 4; j++) ldsm_x4t(blo[j], Bl + brow + bcol0 + j * 32);
#pragma unroll
                for (int i = 0; i < 2; i++)
#pragma unroll
                    for (int jj = 0; jj < 8; jj++)
                        mma_bf16(acc[i][jj], ahi[i],
                                 blo[jj >> 1][(jj & 1) * 2], blo[jj >> 1][(jj & 1) * 2 + 1]);
            }
        }
    };

    // prologue
    issue_chunk(0, 0);
    CP_WAIT0();
    __syncthreads();

    for (int kc = 0; kc < 64; kc++) {
        int nb = kc & 1;
        if (kc < 63) issue_chunk(kc + 1, nb ^ 1);
        compute(nb);
        if (kc < 63) {
            CP_WAIT0();
            __syncthreads();
        }
    }

    // epilogue: BN + ReLU -> g_F[b][hw][cf]
    int jb = w & 1;
    int gid = lane >> 2, tig = lane & 3;
    float* Fb = g_F + (size_t)(b0 + jb) * HW_ * CF_;
#pragma unroll
    for (int i = 0; i < 2; i++) {
        int cfA = m0 + wm + i * 16 + gid;
        int cfB = cfA + 8;
        float scA = gam[cfA] * rsqrtf(var[cfA] + EPS_);
        float bbA = bet[cfA] + (cbias[cfA] - mu[cfA]) * scA;
        float scB = gam[cfB] * rsqrtf(var[cfB] + EPS_);
        float bbB = bet[cfB] + (cbias[cfB] - mu[cfB]) * scB;
#pragma unroll
        for (int jj = 0; jj < 8; jj++) {
            int hw = jj * 8 + tig * 2;
            Fb[(size_t)hw * CF_ + cfA]       = fmaxf(fmaf(acc[i][jj][0], scA, bbA), 0.f);
            Fb[(size_t)(hw + 1) * CF_ + cfA] = fmaxf(fmaf(acc[i][jj][1], scA, bbA), 0.f);
            Fb[(size_t)hw * CF_ + cfB]       = fmaxf(fmaf(acc[i][jj][2], scB, bbB), 0.f);
            Fb[(size_t)(hw + 1) * CF_ + cfB] = fmaxf(fmaf(acc[i][jj][3], scB, bbB), 0.f);
        }
    }
}

// ============================================================
// K2: bilinear gather -> feat (B, J*515). 512 threads, warp-per-joint.
// ============================================================
__global__ void __launch_bounds__(512) k_gather(const float* __restrict__ coords) {
    int b = blockIdx.x;
    __shared__ int   sidx[J_][4];
    __shared__ float swt[J_][4];
    int tid = threadIdx.x;
    if (tid < J_) {
        float x = coords[(b * J_ + tid) * 3 + 0];
        float y = coords[(b * J_ + tid) * 3 + 1];
        float x0f = floorf(x), y0f = floorf(y);
        float wx1 = x - x0f, wy1 = y - y0f;
        float wx0 = 1.f - wx1, wy0 = 1.f - wy1;
        int x0 = (int)x0f, y0 = (int)y0f, x1 = x0 + 1, y1 = y0 + 1;
        int ys[4] = {y0, y0, y1, y1};
        int xs[4] = {x0, x1, x0, x1};
        float ws[4] = {wy0 * wx0, wy0 * wx1, wy1 * wx0, wy1 * wx1};
#pragma unroll
        for (int c = 0; c < 4; c++) {
            bool valid = (xs[c] >= 0) && (xs[c] < 8) && (ys[c] >= 0) && (ys[c] < 8);
            int yc = min(max(ys[c], 0), 7), xc = min(max(xs[c], 0), 7);
            sidx[tid][c] = yc * 8 + xc;
            swt[tid][c] = valid ? ws[c] : 0.f;
        }
    }
    __syncthreads();
    const float4* F4 = (const float4*)(g_F + (size_t)b * HW_ * CF_);
    float* fb = g_feat + (size_t)b * D_;
    int w = tid >> 5, lane = tid & 31;
    for (int j = w; j < J_; j += 16) {
        int i0 = sidx[j][0], i1 = sidx[j][1], i2 = sidx[j][2], i3 = sidx[j][3];
        float w0 = swt[j][0], w1 = swt[j][1], w2 = swt[j][2], w3 = swt[j][3];
        float* dst = fb + j * 515;
#pragma unroll
        for (int q = 0; q < 4; q++) {
            int c4 = lane + q * 32;   // float4 index within 128
            float4 a = F4[i0 * 128 + c4], bb = F4[i1 * 128 + c4];
            float4 c = F4[i2 * 128 + c4], d = F4[i3 * 128 + c4];
            float r0 = w0 * a.x + w1 * bb.x + w2 * c.x + w3 * d.x;
            float r1 = w0 * a.y + w1 * bb.y + w2 * c.y + w3 * d.y;
            float r2 = w0 * a.z + w1 * bb.z + w2 * c.z + w3 * d.z;
            float r3 = w0 * a.w + w1 * bb.w + w2 * c.w + w3 * d.w;
            int cf = c4 * 4;
            dst[cf] = r0; dst[cf + 1] = r1; dst[cf + 2] = r2; dst[cf + 3] = r3;
        }
    }
    for (int t = tid; t < J_ * 3; t += 512) {
        int j = t / 3, c = t % 3;
        fb[j * 515 + 512 + c] = coords[(b * J_ + j) * 3 + c];
    }
}

// ============================================================
// K3: big linear heads (root 6 + pose 126), K=15450, ksplit=6
// ============================================================
#define KC3 32
__global__ void __launch_bounds__(256) k_bigmm(const float* __restrict__ rw,
                                               const float* __restrict__ pw) {
    int o0 = blockIdx.x * 32;
    int b0 = blockIdx.y * 64;
    int ks = blockIdx.z;
    int kbeg = ks * 2575, kend = kbeg + 2575;
    __shared__ float At[KC3][65];
    __shared__ float Bt[KC3][33];
    int tid = threadIdx.x;
    int tx = tid & 7;
    int ty = tid >> 3;
    float acc[2][4];
#pragma unroll
    for (int i = 0; i < 2; i++)
#pragma unroll
        for (int j = 0; j < 4; j++) acc[i][j] = 0.f;

    for (int kk = kbeg; kk < kend; kk += KC3) {
#pragma unroll
        for (int i = 0; i < 8; i++) {
            int idx = tid + i * 256;
            int m = idx >> 5, k = idx & 31;
            int kg = kk + k;
            At[k][m] = (kg < kend) ? g_feat[(size_t)(b0 + m) * D_ + kg] : 0.f;
        }
#pragma unroll
        for (int i = 0; i < 4; i++) {
            int idx = tid + i * 256;
            int n = idx >> 5, k = idx & 31;
            int o = o0 + n, kg = kk + k;
            float v = 0.f;
            if (o < 132 && kg < kend) {
                const float* wr = (o < 6) ? (rw + (size_t)o * D_)
                                          : (pw + (size_t)(o - 6) * D_);
                v = wr[kg];
            }
            Bt[k][n] = v;
        }
        __syncthreads();
#pragma unroll
        for (int k = 0; k < KC3; k++) {
            float a0 = At[k][ty * 2], a1 = At[k][ty * 2 + 1];
#pragma unroll
            for (int j = 0; j < 4; j++) {
                float bj = Bt[k][tx * 4 + j];
                acc[0][j] += a0 * bj;
                acc[1][j] += a1 * bj;
            }
        }
        __syncthreads();
    }
#pragma unroll
    for (int i = 0; i < 2; i++) {
        int b = b0 + ty * 2 + i;
#pragma unroll
        for (int j = 0; j < 4; j++) {
            int o = o0 + tx * 4 + j;
            if (o < 132)
                g_part[((size_t)ks * B_ + b) * 132 + o] = acc[i][j];
        }
    }
}

__global__ void k_reduce(const float* __restrict__ rb, const float* __restrict__ pb,
                         float* __restrict__ out) {
    int i = blockIdx.x * 256 + threadIdx.x;
    if (i >= B_ * 132) return;
    int b = i / 132, o = i % 132;
    float s = 0.f;
#pragma unroll
    for (int ks = 0; ks < 6; ks++) s += g_part[((size_t)ks * B_ + b) * 132 + o];
    if (o < 6) out[b * 6 + o] = s + rb[o];
    else       out[3072 + b * 126 + (o - 6)] = s + pb[o - 6];
}

// ============================================================
extern "C" void kernel_launch(void* const* d_in, const int* in_sizes, int n_in,
                              void* d_out, int out_size) {
    const float* img    = (const float*)d_in[0];
    const float* coords = (const float*)d_in[1];
    const float* conv_w = (const float*)d_in[2];
    const float* conv_b = (const float*)d_in[3];
    const float* gam    = (const float*)d_in[4];
    const float* bet    = (const float*)d_in[5];
    const float* mu     = (const float*)d_in[6];
    const float* var    = (const float*)d_in[7];
    const float* root_w = (const float*)d_in[8];
    const float* root_b = (const float*)d_in[9];
    const float* pose_w = (const float*)d_in[10];
    const float* pose_b = (const float*)d_in[11];
    const float* shp_w  = (const float*)d_in[12];
    const float* shp_b  = (const float*)d_in[13];
    const float* cam_w  = (const float*)d_in[14];
    const float* cam_b  = (const float*)d_in[15];
    float* out = (float*)d_out;

    cudaFuncSetAttribute(k_conv_mma, cudaFuncAttributeMaxDynamicSharedMemorySize, SMEM_CONV);

    k_prep_w<<<2048, 256>>>(conv_w);
    k_prep_x<<<65536, 256>>>(img);                   // also computes g_pooled
    k_heads<<<B_, 128>>>(shp_w, shp_b, cam_w, cam_b, out);
    k_conv_mma<<<dim3(4, 256), 256, SMEM_CONV>>>(conv_b, gam, bet, mu, var);
    k_gather<<<B_, 512>>>(coords);
    k_bigmm<<<dim3(5, 8, 6), 256>>>(root_w, pose_w);
    k_reduce<<<(B_ * 132 + 255) / 256, 256>>>(root_b, pose_b, out);
}